// round 12
// baseline (speedup 1.0000x reference)
#include <cuda_runtime.h>
#include <cuda_bf16.h>
#include <cstdint>

#define MAX_D 8192
__device__ __align__(128) float g_mask[MAX_D];
__device__ unsigned int g_done;   // reset to 0 via cudaMemsetAsync each call

// ---------------------------------------------------------------------------
// Fused kernel. R7 poly memory shape (4x float4/thread, block-strided,
// __ldcs/__stcs) + mask on blocks [0, maskBlocks) + flag sync where the poll
// hides under the in-flight x loads.
//
// Mask: exact lax.top_k tie semantics:
//   rank(d) = #{j: imp[j] > imp[d]} + #{j < d: imp[j] == imp[d]}
//   mask[d] = rank < keep
// Requires: D <= 4096, D % 256 == 0, maskBlocks = D/16 <= gridDim.x.
// ---------------------------------------------------------------------------
__global__ void __launch_bounds__(256)
fused_kernel(const float4* __restrict__ x,
             const float* __restrict__ coeffs,
             float4* __restrict__ out,
             int n4, unsigned int d4_mask,
             const float* __restrict__ imp, int D, int keep, int maskBlocks) {
    __shared__ float s_imp[4096];          // 16 KB (mask blocks only populate)
    __shared__ int   s_part[16][17];

    const int tid = threadIdx.x;

    // ---- Phase A: mask (first maskBlocks blocks only; wave-1 by dispatch) --
    if ((int)blockIdx.x < maskBlocks) {
        for (int j = tid; j < D; j += blockDim.x) s_imp[j] = imp[j];
        __syncthreads();

        int chIdx = tid & 15;              // channel within block
        int sl    = tid >> 4;              // j-slice 0..15
        int d     = blockIdx.x * 16 + chIdx;
        float v   = s_imp[d];

        int chunk = D >> 4;                // 256 @ D=4096
        int base  = sl * chunk;
        int cnt = 0;
        #pragma unroll 8
        for (int j = 0; j < chunk; j++) {
            int jj = base + j;
            float u = s_imp[jj];
            cnt += (u > v) ? 1 : ((u == v && jj < d) ? 1 : 0);
        }
        s_part[sl][chIdx] = cnt;
        __syncthreads();

        if (tid < 16) {
            int r = 0;
            #pragma unroll
            for (int s = 0; s < 16; s++) r += s_part[s][tid];
            g_mask[blockIdx.x * 16 + tid] = (r < keep) ? 1.0f : 0.0f;
        }
        __threadfence();                   // publish g_mask before counting
        __syncthreads();
        if (tid == 0) atomicAdd(&g_done, 1u);
    }

    // ---- Phase B: issue coalesced streaming loads (front-batched, MLP=4) --
    const int base = blockIdx.x * 1024 + tid;
    int  idx[4];
    bool act[4];
    #pragma unroll
    for (int k = 0; k < 4; k++) {
        idx[k] = base + k * 256;
        act[k] = (idx[k] < n4);
    }

    float4 xv[4];
    #pragma unroll
    for (int k = 0; k < 4; k++)
        xv[k] = act[k] ? __ldcs(&x[idx[k]]) : make_float4(0.f, 0.f, 0.f, 0.f);

    float c0 = __ldg(&coeffs[0]);
    float c1 = __ldg(&coeffs[1]);
    float c2 = __ldg(&coeffs[2]);

    // ---- Phase C: wait for mask — poll hides under the load latency -------
    if (tid == 0) {
        unsigned int v;
        do {
            asm volatile("ld.acquire.gpu.u32 %0, [%1];"
                         : "=r"(v) : "l"(&g_done) : "memory");
            if ((int)v >= maskBlocks) break;
            __nanosleep(64);
        } while (true);
    }
    __syncthreads();

    // ---- Phase D: poly + select + streaming store --------------------------
    const float4* m4 = reinterpret_cast<const float4*>(g_mask);
    #pragma unroll
    for (int k = 0; k < 4; k++) {
        if (act[k]) {
            float4 mv = m4[idx[k] & d4_mask];
            float4 r;
            float p;
            p = xv[k].x * fmaf(xv[k].x, fmaf(xv[k].x, c2, c1), c0);
            r.x = fmaf(mv.x, p - xv[k].x, xv[k].x);
            p = xv[k].y * fmaf(xv[k].y, fmaf(xv[k].y, c2, c1), c0);
            r.y = fmaf(mv.y, p - xv[k].y, xv[k].y);
            p = xv[k].z * fmaf(xv[k].z, fmaf(xv[k].z, c2, c1), c0);
            r.z = fmaf(mv.z, p - xv[k].z, xv[k].z);
            p = xv[k].w * fmaf(xv[k].w, fmaf(xv[k].w, c2, c1), c0);
            r.w = fmaf(mv.w, p - xv[k].w, xv[k].w);
            __stcs(&out[idx[k]], r);
        }
    }
}

// ---------------------------------------------------------------------------
// Fallback path (scalar, any shape).
// ---------------------------------------------------------------------------
__global__ void mask_kernel_fb(const float* __restrict__ imp, int D, int keep) {
    int d = blockIdx.x * blockDim.x + threadIdx.x;
    if (d >= D) return;
    float v = imp[d];
    int cnt = 0;
    for (int j = 0; j < D; j++) {
        float u = imp[j];
        cnt += (u > v) ? 1 : ((u == v && j < d) ? 1 : 0);
    }
    g_mask[d] = (cnt < keep) ? 1.0f : 0.0f;
}

__global__ void poly_kernel_fb(const float* __restrict__ x,
                               const float* __restrict__ coeffs,
                               float* __restrict__ out, int n, int D) {
    int i = blockIdx.x * blockDim.x + threadIdx.x;
    if (i >= n) return;
    float c0 = coeffs[0], c1 = coeffs[1], c2 = coeffs[2];
    float xv = x[i];
    float m = g_mask[i % D];
    float p = xv * fmaf(xv, fmaf(xv, c2, c1), c0);
    out[i] = fmaf(m, p - xv, xv);
}

extern "C" void kernel_launch(void* const* d_in, const int* in_sizes, int n_in,
                              void* d_out, int out_size) {
    const float* x    = (const float*)d_in[0];   // (B, T, D) fp32
    const float* coef = (const float*)d_in[1];   // (3,) fp32
    const float* imp  = (const float*)d_in[2];   // (D,) fp32

    int D    = in_sizes[2];                      // 4096
    int keep = (int)(D * 0.5);
    if (keep < 1) keep = 1;
    int n    = in_sizes[0];                      // B*T*D

    int n4 = n / 4;
    int threads = 256;
    int blocks  = (n4 + 1023) / 1024;            // 16384 @ n=64M
    int maskBlocks = D / 16;                     // 256

    bool fast_ok = (D <= 4096) && (D % 256 == 0) && ((D & (D - 1)) == 0) &&
                   (n % 4 == 0) && (blocks >= maskBlocks);

    if (!fast_ok) {
        mask_kernel_fb<<<(D + 255) / 256, 256>>>(imp, D, keep);
        poly_kernel_fb<<<(n + 255) / 256, 256>>>(x, coef, (float*)d_out, n, D);
        return;
    }

    // Reset arrival counter (graph-capturable memset node).
    void* done_addr = nullptr;
    cudaGetSymbolAddress(&done_addr, g_done);
    cudaMemsetAsync(done_addr, 0, sizeof(unsigned int), 0);

    unsigned int d4_mask = (unsigned int)(D / 4) - 1u;
    fused_kernel<<<blocks, threads>>>((const float4*)x, coef,
                                      (float4*)d_out, n4, d4_mask,
                                      imp, D, keep, maskBlocks);
}

// round 13
// speedup vs baseline: 1.0331x; 1.0331x over previous
#include <cuda_runtime.h>
#include <cuda_bf16.h>
#include <cstdint>

#define MAX_D 8192
__device__ __align__(128) float g_mask[MAX_D];

// ---------------------------------------------------------------------------
// Kernel 1 (unchanged from R10, proven): exact top-k channel mask,
// lax.top_k tie-breaking. rank(d) = #{j: imp[j] > imp[d]} + #{j<d: ==}.
// Grid: D/16 blocks x 256 threads. Assumes D <= 4096, D % 256 == 0.
// ---------------------------------------------------------------------------
__global__ void __launch_bounds__(256)
mask_kernel(const float* __restrict__ imp, int D, int keep) {
    __shared__ float s_imp[4096];          // 16 KB
    __shared__ int   s_part[16][17];

    int tid = threadIdx.x;
    for (int j = tid; j < D; j += blockDim.x) s_imp[j] = imp[j];
    __syncthreads();

    int chIdx = tid & 15;
    int sl    = tid >> 4;
    int d     = blockIdx.x * 16 + chIdx;
    float v   = s_imp[d];

    int chunk = D >> 4;
    int base  = sl * chunk;
    int cnt = 0;
    #pragma unroll 8
    for (int j = 0; j < chunk; j++) {
        int jj = base + j;
        float u = s_imp[jj];
        cnt += (u > v) ? 1 : ((u == v && jj < d) ? 1 : 0);
    }
    s_part[sl][chIdx] = cnt;
    __syncthreads();

    if (tid < 16) {
        int r = 0;
        #pragma unroll
        for (int s = 0; s < 16; s++) r += s_part[s][tid];
        g_mask[blockIdx.x * 16 + tid] = (r < keep) ? 1.0f : 0.0f;
    }

    __threadfence();
    __syncthreads();
    cudaTriggerProgrammaticLaunchCompletion();
}

// ---------------------------------------------------------------------------
// Kernel 2: streaming polynomial, 8x float4 per thread, BLOCK-STRIDED
// (i_k = bid*2048 + tid + k*256 — every LDG/STG fully coalesced, MLP_p1=8).
// All 8 loads issued before the grid-dependency sync (PDL overlap w/ mask).
// Poly evaluated inline at store time to cap register pressure.
// y = x + m*(poly(x) - x),  poly = x*(c0 + x*(c1 + x*c2))
// ---------------------------------------------------------------------------
__global__ void __launch_bounds__(256)
poly_kernel(const float4* __restrict__ x,
            const float* __restrict__ coeffs,
            float4* __restrict__ out,
            int n4, unsigned int d4_mask) {
    const int base = blockIdx.x * 2048 + threadIdx.x;

    // Pre-sync: 8 coalesced streaming loads, front-batched.
    float4 xv[8];
    #pragma unroll
    for (int k = 0; k < 8; k++) {
        int idx = base + k * 256;
        xv[k] = (idx < n4) ? __ldcs(&x[idx]) : make_float4(0.f, 0.f, 0.f, 0.f);
    }

    float c0 = __ldg(&coeffs[0]);
    float c1 = __ldg(&coeffs[1]);
    float c2 = __ldg(&coeffs[2]);

    cudaGridDependencySynchronize();

    const float4* m4 = reinterpret_cast<const float4*>(g_mask);
    #pragma unroll
    for (int k = 0; k < 8; k++) {
        int idx = base + k * 256;
        if (idx < n4) {
            float4 mv = m4[idx & d4_mask];
            float4 r;
            float p;
            p = xv[k].x * fmaf(xv[k].x, fmaf(xv[k].x, c2, c1), c0);
            r.x = fmaf(mv.x, p - xv[k].x, xv[k].x);
            p = xv[k].y * fmaf(xv[k].y, fmaf(xv[k].y, c2, c1), c0);
            r.y = fmaf(mv.y, p - xv[k].y, xv[k].y);
            p = xv[k].z * fmaf(xv[k].z, fmaf(xv[k].z, c2, c1), c0);
            r.z = fmaf(mv.z, p - xv[k].z, xv[k].z);
            p = xv[k].w * fmaf(xv[k].w, fmaf(xv[k].w, c2, c1), c0);
            r.w = fmaf(mv.w, p - xv[k].w, xv[k].w);
            __stcs(&out[idx], r);
        }
    }
}

// ---------------------------------------------------------------------------
// Fallback path (scalar, any shape).
// ---------------------------------------------------------------------------
__global__ void mask_kernel_fb(const float* __restrict__ imp, int D, int keep) {
    int d = blockIdx.x * blockDim.x + threadIdx.x;
    if (d >= D) return;
    float v = imp[d];
    int cnt = 0;
    for (int j = 0; j < D; j++) {
        float u = imp[j];
        cnt += (u > v) ? 1 : ((u == v && j < d) ? 1 : 0);
    }
    g_mask[d] = (cnt < keep) ? 1.0f : 0.0f;
}

__global__ void poly_kernel_fb(const float* __restrict__ x,
                               const float* __restrict__ coeffs,
                               float* __restrict__ out, int n, int D) {
    int i = blockIdx.x * blockDim.x + threadIdx.x;
    if (i >= n) return;
    float c0 = coeffs[0], c1 = coeffs[1], c2 = coeffs[2];
    float xv = x[i];
    float m = g_mask[i % D];
    float p = xv * fmaf(xv, fmaf(xv, c2, c1), c0);
    out[i] = fmaf(m, p - xv, xv);
}

extern "C" void kernel_launch(void* const* d_in, const int* in_sizes, int n_in,
                              void* d_out, int out_size) {
    const float* x    = (const float*)d_in[0];   // (B, T, D) fp32
    const float* coef = (const float*)d_in[1];   // (3,) fp32
    const float* imp  = (const float*)d_in[2];   // (D,) fp32

    int D    = in_sizes[2];                      // 4096
    int keep = (int)(D * 0.5);
    if (keep < 1) keep = 1;
    int n    = in_sizes[0];                      // B*T*D

    bool fast_ok = (D <= 4096) && (D % 256 == 0) && ((D & (D - 1)) == 0) &&
                   (n % 4 == 0);

    if (!fast_ok) {
        mask_kernel_fb<<<(D + 255) / 256, 256>>>(imp, D, keep);
        poly_kernel_fb<<<(n + 255) / 256, 256>>>(x, coef, (float*)d_out, n, D);
        return;
    }

    // Kernel 1: exact-rank mask.
    mask_kernel<<<D / 16, 256>>>(imp, D, keep);

    // Kernel 2: streaming poly (8 float4/thread, block-strided) with PDL.
    {
        int n4 = n / 4;
        unsigned int d4_mask = (unsigned int)(D / 4) - 1u;
        int threads = 256;
        int blocks  = (n4 + 2047) / 2048;        // 8192 @ n=64M

        cudaLaunchAttribute attrs[1];
        attrs[0].id = cudaLaunchAttributeProgrammaticStreamSerialization;
        attrs[0].val.programmaticStreamSerializationAllowed = 1;

        cudaLaunchConfig_t cfg = {};
        cfg.gridDim  = dim3((unsigned)blocks, 1, 1);
        cfg.blockDim = dim3((unsigned)threads, 1, 1);
        cfg.dynamicSmemBytes = 0;
        cfg.stream   = 0;
        cfg.attrs    = attrs;
        cfg.numAttrs = 1;

        cudaError_t err = cudaLaunchKernelEx(&cfg, poly_kernel,
                                             (const float4*)x, coef,
                                             (float4*)d_out, n4, d4_mask);
        if (err != cudaSuccess) {
            poly_kernel<<<blocks, threads>>>((const float4*)x, coef,
                                             (float4*)d_out, n4, d4_mask);
        }
    }
}

// round 14
// speedup vs baseline: 1.0408x; 1.0075x over previous
#include <cuda_runtime.h>
#include <cuda_bf16.h>
#include <cstdint>

#define MAX_D 8192
__device__ __align__(128) float g_mask[MAX_D];   // sentinel 0xFFFFFFFF per call

// ---------------------------------------------------------------------------
// Fused kernel, barrier-free.
// Grid remap: chGroups = D4/256 channel-groups per 4-row band.
//   bid -> rowgrp = bid / chGroups, cg = bid % chGroups
//   thread t handles ch4 = cg*256 + t for rows rowgrp*4 .. rowgrp*4+3
// => one mask float4 per thread, every LDG/STG 512 B/warp coalesced.
// Blocks [0, maskBlocks): first compute the exact top-k mask
//   rank(d) = #{j: imp[j] > imp[d]} + #{j<d: imp[j]==imp[d]}, mask = rank<keep
// (exact lax.top_k tie semantics), store + threadfence, then do their tile.
// All blocks: issue 4 x-loads, then value-spin (ld.cg) on their mask vector
// until no lane is the sentinel. No flags, no barriers, no acquire.
// Requires: D % 1024 == 0, D <= 8192, n == rows*D with rows % 4 == 0,
//           maskBlocks = D/16 <= gridDim.x.
// ---------------------------------------------------------------------------
__global__ void __launch_bounds__(256)
fused_kernel(const float4* __restrict__ x,
             const float* __restrict__ coeffs,
             float4* __restrict__ out,
             int D4, int chGroups,
             const float* __restrict__ imp, int D, int keep, int maskBlocks) {
    __shared__ float s_imp[4096];          // mask blocks only populate
    __shared__ int   s_part[16][17];

    const int tid = threadIdx.x;

    // ---- Phase A: mask on first maskBlocks blocks (wave-1 by dispatch) ----
    if ((int)blockIdx.x < maskBlocks) {
        for (int j = tid; j < D; j += blockDim.x) s_imp[j] = imp[j];
        __syncthreads();

        int chIdx = tid & 15;
        int sl    = tid >> 4;
        int d     = blockIdx.x * 16 + chIdx;
        float v   = s_imp[d];

        int chunk = D >> 4;
        int base  = sl * chunk;
        int cnt = 0;
        #pragma unroll 8
        for (int j = 0; j < chunk; j++) {
            int jj = base + j;
            float u = s_imp[jj];
            cnt += (u > v) ? 1 : ((u == v && jj < d) ? 1 : 0);
        }
        s_part[sl][chIdx] = cnt;
        __syncthreads();

        if (tid < 16) {
            int r = 0;
            #pragma unroll
            for (int s = 0; s < 16; s++) r += s_part[s][tid];
            g_mask[blockIdx.x * 16 + tid] = (r < keep) ? 1.0f : 0.0f;
        }
        __threadfence();                   // push mask words to gpu scope
    }

    // ---- Phase B: tile indices + front-batched coalesced loads ------------
    const int rowgrp = (int)blockIdx.x / chGroups;
    const int cg     = (int)blockIdx.x % chGroups;
    const int ch4    = cg * 256 + tid;               // float4 channel column
    const int row0   = rowgrp * 4;
    const long long b0 = (long long)row0 * D4 + ch4;

    float4 xv[4];
    #pragma unroll
    for (int r = 0; r < 4; r++)
        xv[r] = __ldcs(&x[b0 + (long long)r * D4]);

    float c0 = __ldg(&coeffs[0]);
    float c1 = __ldg(&coeffs[1]);
    float c2 = __ldg(&coeffs[2]);

    // ---- Phase C: value-spin on this thread's mask vector (L2, ld.cg) -----
    unsigned mx, my, mz, mw;
    {
        const float4* mp = reinterpret_cast<const float4*>(g_mask) + ch4;
        int slp = 0;
        while (true) {
            asm volatile("ld.global.cg.v4.u32 {%0,%1,%2,%3}, [%4];"
                         : "=r"(mx), "=r"(my), "=r"(mz), "=r"(mw)
                         : "l"(mp) : "memory");
            if (mx != 0xFFFFFFFFu && my != 0xFFFFFFFFu &&
                mz != 0xFFFFFFFFu && mw != 0xFFFFFFFFu) break;
            slp = (slp < 256) ? slp + 64 : 256;
            __nanosleep(slp);
        }
    }
    float4 mv;
    mv.x = __uint_as_float(mx);
    mv.y = __uint_as_float(my);
    mv.z = __uint_as_float(mz);
    mv.w = __uint_as_float(mw);

    // ---- Phase D: poly + select + streaming store -------------------------
    #pragma unroll
    for (int r = 0; r < 4; r++) {
        float4 rr;
        float p;
        p = xv[r].x * fmaf(xv[r].x, fmaf(xv[r].x, c2, c1), c0);
        rr.x = fmaf(mv.x, p - xv[r].x, xv[r].x);
        p = xv[r].y * fmaf(xv[r].y, fmaf(xv[r].y, c2, c1), c0);
        rr.y = fmaf(mv.y, p - xv[r].y, xv[r].y);
        p = xv[r].z * fmaf(xv[r].z, fmaf(xv[r].z, c2, c1), c0);
        rr.z = fmaf(mv.z, p - xv[r].z, xv[r].z);
        p = xv[r].w * fmaf(xv[r].w, fmaf(xv[r].w, c2, c1), c0);
        rr.w = fmaf(mv.w, p - xv[r].w, xv[r].w);
        __stcs(&out[b0 + (long long)r * D4], rr);
    }
}

// ---------------------------------------------------------------------------
// Fallback path (scalar, any shape).
// ---------------------------------------------------------------------------
__global__ void mask_kernel_fb(const float* __restrict__ imp, int D, int keep) {
    int d = blockIdx.x * blockDim.x + threadIdx.x;
    if (d >= D) return;
    float v = imp[d];
    int cnt = 0;
    for (int j = 0; j < D; j++) {
        float u = imp[j];
        cnt += (u > v) ? 1 : ((u == v && j < d) ? 1 : 0);
    }
    g_mask[d] = (cnt < keep) ? 1.0f : 0.0f;
}

__global__ void poly_kernel_fb(const float* __restrict__ x,
                               const float* __restrict__ coeffs,
                               float* __restrict__ out, int n, int D) {
    int i = blockIdx.x * blockDim.x + threadIdx.x;
    if (i >= n) return;
    float c0 = coeffs[0], c1 = coeffs[1], c2 = coeffs[2];
    float xv = x[i];
    float m = g_mask[i % D];
    float p = xv * fmaf(xv, fmaf(xv, c2, c1), c0);
    out[i] = fmaf(m, p - xv, xv);
}

extern "C" void kernel_launch(void* const* d_in, const int* in_sizes, int n_in,
                              void* d_out, int out_size) {
    const float* x    = (const float*)d_in[0];   // (B, T, D) fp32
    const float* coef = (const float*)d_in[1];   // (3,) fp32
    const float* imp  = (const float*)d_in[2];   // (D,) fp32

    int D    = in_sizes[2];                      // 4096
    int keep = (int)(D * 0.5);
    if (keep < 1) keep = 1;
    int n    = in_sizes[0];                      // B*T*D

    int D4       = D / 4;                        // 1024
    int chGroups = D4 / 256;                     // 4
    long long rows = (D > 0) ? (long long)n / D : 0;
    int maskBlocks = D / 16;                     // 256
    long long blocksLL = (rows / 4) * chGroups;  // 16384 @ 64M

    bool fast_ok = (D <= 4096) && (D % 1024 == 0) &&
                   (rows > 0) && ((long long)rows * D == n) &&
                   (rows % 4 == 0) && (blocksLL >= maskBlocks) &&
                   (blocksLL <= 0x7FFFFFFFLL);

    if (!fast_ok) {
        mask_kernel_fb<<<(D + 255) / 256, 256>>>(imp, D, keep);
        poly_kernel_fb<<<(n + 255) / 256, 256>>>(x, coef, (float*)d_out, n, D);
        return;
    }

    // Reset g_mask to sentinel 0xFFFFFFFF (graph-capturable memset node).
    void* mask_addr = nullptr;
    cudaGetSymbolAddress(&mask_addr, g_mask);
    cudaMemsetAsync(mask_addr, 0xFF, (size_t)D * sizeof(float), 0);

    fused_kernel<<<(int)blocksLL, 256>>>((const float4*)x, coef,
                                         (float4*)d_out, D4, chGroups,
                                         imp, D, keep, maskBlocks);
}